// round 15
// baseline (speedup 1.0000x reference)
#include <cuda_runtime.h>
#include <cuda_fp16.h>

// Problem constants (fixed by the dataset)
#define Nn 10000
#define Tt 6
#define Ff 64
#define Ee 160000
#define EP 170000   // Ee + Nn self loops
#define FULLMASK 0xffffffffu

// ---------------- scratch (device globals; no allocations allowed) -------------
__device__ __align__(16) __half g_xw0[Nn * 64];        // layer0 features (fp16)
__device__ __align__(16) float  g_h0[Nn * 64];
__device__ __align__(16) __half g_xw1[Nn * 256];       // layer1 features (fp16)
__device__ __align__(16) float  g_ssrc[Nn * 4];
__device__ __align__(16) float  g_sdst[Nn * 4];
__device__ __align__(16) float  g_alpha[EP * 4];       // slow-path stash only
__device__ __align__(16) float  g_ht[Tt * Nn * 64];
__device__ __align__(16) float  g_gi[(size_t)Tt * Nn * 192];
__device__ float g_Wt_ih[64 * 192];
__device__ float g_Wt_hh[64 * 192];
__device__ int g_deg[Nn];
__device__ int g_rowptr[Nn + 1];
__device__ int g_cursor[Nn];
__device__ int g_csr_src[EP];
__device__ int g_csr_dst[EP];
__device__ int g_csr_eid[EP];

// ---------------- inline edge dtype detect (one thread/block, shared flag) ------
__device__ __forceinline__ int block_detect64(const void* ei) {
    __shared__ int sIs64;
    if (threadIdx.x == 0) {
        const int* w = (const int*)ei;
        int zeros = 0;
#pragma unroll
        for (int i = 0; i < 16; i++)
            if (w[2 * i + 1] == 0) zeros++;
        sIs64 = (zeros > 8) ? 1 : 0;
    }
    __syncthreads();
    return sIs64;
}

__device__ __forceinline__ int edge_val(const void* ei, int idx, int is64) {
    if (is64) return (int)((const long long*)ei)[idx];
    return ((const int*)ei)[idx];
}

// ---------------- init: zero deg, transpose GRU weights -------------------------
__global__ void k_init(const float* __restrict__ W_ih, const float* __restrict__ W_hh) {
    int i = blockIdx.x * 256 + threadIdx.x;
    if (i < Nn) g_deg[i] = 0;
    if (i < 192 * 64) {
        int kk = i / 64, j = i % 64;
        g_Wt_ih[j * 192 + kk] = W_ih[i];
        g_Wt_hh[j * 192 + kk] = W_hh[i];
    }
}

// ---------------- CSR build (dst-major) -----------------------------------------
__global__ void k_count(const void* __restrict__ ei) {
    int is64 = block_detect64(ei);
    int e = blockIdx.x * 256 + threadIdx.x;
    if (e >= EP) return;
    int d = (e < Ee) ? edge_val(ei, Ee + e, is64) : (e - Ee);
    atomicAdd(&g_deg[d], 1);
}

__global__ void k_scan() {
    __shared__ int wsum[32];
    int tid = threadIdx.x;
    const int IT = 10;
    int base = tid * IT;
    int vals[IT];
    int s = 0;
#pragma unroll
    for (int i = 0; i < IT; i++) {
        int idx = base + i;
        int v = (idx < Nn) ? g_deg[idx] : 0;
        vals[i] = s;
        s += v;
    }
    int lane = tid & 31, w = tid >> 5;
    int inc = s;
    for (int o = 1; o < 32; o <<= 1) {
        int y = __shfl_up_sync(FULLMASK, inc, o);
        if (lane >= o) inc += y;
    }
    if (lane == 31) wsum[w] = inc;
    __syncthreads();
    if (w == 0) {
        int v = wsum[lane];
        for (int o = 1; o < 32; o <<= 1) {
            int y = __shfl_up_sync(FULLMASK, v, o);
            if (lane >= o) v += y;
        }
        wsum[lane] = v;
    }
    __syncthreads();
    int excl = inc - s + ((w > 0) ? wsum[w - 1] : 0);
#pragma unroll
    for (int i = 0; i < IT; i++) {
        int idx = base + i;
        if (idx < Nn) {
            g_rowptr[idx] = excl + vals[i];
            g_cursor[idx] = excl + vals[i];
        }
    }
    if (tid == 1023) g_rowptr[Nn] = wsum[31];
}

__global__ void k_scatter(const void* __restrict__ ei) {
    int is64 = block_detect64(ei);
    int e = blockIdx.x * 256 + threadIdx.x;
    if (e >= EP) return;
    int s = (e < Ee) ? edge_val(ei, e, is64) : (e - Ee);
    int d = (e < Ee) ? edge_val(ei, Ee + e, is64) : (e - Ee);
    int p = atomicAdd(&g_cursor[d], 1);
    g_csr_src[p] = s;
    g_csr_dst[p] = d;
    g_csr_eid[p] = e;
}

// ---------------- GAT layer 0 GEMM + head sums (32 rows/block) ------------------
__global__ void k_l0_gemm(const float* __restrict__ x, const float* __restrict__ W0,
                          const float* __restrict__ a_src, const float* __restrict__ a_dst,
                          int t) {
    __shared__ float sW[64 * 64];
    __shared__ __align__(16) float sx[32][64];
    int tid = threadIdx.x;
    int n0 = blockIdx.x * 32;
    for (int i = tid; i < 64 * 64; i += 256) sW[i] = W0[i];
    for (int i = tid; i < 32 * 64; i += 256) {
        int r = i >> 6, c = i & 63;
        int n = n0 + r;
        sx[r][c] = (n < Nn) ? x[(size_t)n * (Tt * Ff) + t * Ff + c] : 0.f;
    }
    __syncthreads();
    int r4 = tid >> 6, c = tid & 63;
    float acc[8];
#pragma unroll
    for (int q = 0; q < 8; q++) acc[q] = 0.f;
#pragma unroll
    for (int j4 = 0; j4 < 16; j4++) {
        float w0 = sW[(4 * j4 + 0) * 64 + c];
        float w1 = sW[(4 * j4 + 1) * 64 + c];
        float w2 = sW[(4 * j4 + 2) * 64 + c];
        float w3 = sW[(4 * j4 + 3) * 64 + c];
#pragma unroll
        for (int q = 0; q < 8; q++) {
            float4 xv = *(const float4*)&sx[r4 + 4 * q][4 * j4];
            acc[q] += xv.x * w0 + xv.y * w1 + xv.z * w2 + xv.w * w3;
        }
    }
    float as = a_src[c], ad = a_dst[c];
#pragma unroll
    for (int q = 0; q < 8; q++) {
        int row = n0 + r4 + 4 * q;
        float pr = acc[q] * as, pd = acc[q] * ad;
#pragma unroll
        for (int o = 8; o > 0; o >>= 1) {
            pr += __shfl_down_sync(FULLMASK, pr, o);
            pd += __shfl_down_sync(FULLMASK, pd, o);
        }
        if (row < Nn) {
            g_xw0[row * 64 + c] = __float2half(acc[q]);
            if ((c & 15) == 0) {
                g_ssrc[row * 4 + (c >> 4)] = pr;
                g_sdst[row * 4 + (c >> 4)] = pd;
            }
        }
    }
}

// ---------------- GAT layer 1 GEMM + head sums (32 rows/block) ------------------
__global__ void k_l1_gemm(const float* __restrict__ W1, const float* __restrict__ a_src,
                          const float* __restrict__ a_dst) {
    __shared__ __align__(16) float sx[32][64];
    __shared__ float rs[32][8], rd[32][8];
    int tid = threadIdx.x;  // 256
    int n0 = blockIdx.x * 32;
    for (int i = tid; i < 32 * 64; i += 256) {
        int r = i >> 6, c = i & 63;
        int n = n0 + r;
        sx[r][c] = (n < Nn) ? g_h0[n * 64 + c] : 0.f;
    }
    __syncthreads();
    float acc[32];
#pragma unroll
    for (int r = 0; r < 32; r++) acc[r] = 0.f;
#pragma unroll 4
    for (int j4 = 0; j4 < 16; j4++) {
        float w0 = W1[(4 * j4 + 0) * 256 + tid];
        float w1 = W1[(4 * j4 + 1) * 256 + tid];
        float w2 = W1[(4 * j4 + 2) * 256 + tid];
        float w3 = W1[(4 * j4 + 3) * 256 + tid];
#pragma unroll
        for (int r = 0; r < 32; r++) {
            float4 xv = *(const float4*)&sx[r][4 * j4];
            acc[r] += xv.x * w0 + xv.y * w1 + xv.z * w2 + xv.w * w3;
        }
    }
    float as = a_src[tid], ad = a_dst[tid];
    int lane = tid & 31, w8 = tid >> 5;
#pragma unroll
    for (int r = 0; r < 32; r++) {
        int n = n0 + r;
        if (n < Nn) g_xw1[(size_t)n * 256 + tid] = __float2half(acc[r]);
        float pr = acc[r] * as, pd = acc[r] * ad;
#pragma unroll
        for (int o = 16; o > 0; o >>= 1) {
            pr += __shfl_down_sync(FULLMASK, pr, o);
            pd += __shfl_down_sync(FULLMASK, pd, o);
        }
        if (lane == 0) { rs[r][w8] = pr; rd[r][w8] = pd; }
    }
    __syncthreads();
    if (tid < 128) {
        int r = tid >> 2, h = tid & 3;
        int n = n0 + r;
        if (n < Nn) {
            g_ssrc[n * 4 + h] = rs[r][2 * h] + rs[r][2 * h + 1];
            g_sdst[n * 4 + h] = rd[r][2 * h] + rd[r][2 * h + 1];
        }
    }
}

// ---------------- slow-path softmax helper (deg > 32): 3-pass via g_alpha -------
__device__ void softmax_slow(int p0, int p1, int lane, float4 sd,
                             float* __restrict__ outAlpha) {
    float m0 = -1e30f, m1 = -1e30f, m2 = -1e30f, m3 = -1e30f;
    for (int p = p0 + lane; p < p1; p += 32) {
        float4 a = ((const float4*)g_ssrc)[g_csr_src[p]];
        float l0 = a.x + sd.x; l0 = l0 > 0.f ? l0 : 0.2f * l0;
        float l1 = a.y + sd.y; l1 = l1 > 0.f ? l1 : 0.2f * l1;
        float l2 = a.z + sd.z; l2 = l2 > 0.f ? l2 : 0.2f * l2;
        float l3 = a.w + sd.w; l3 = l3 > 0.f ? l3 : 0.2f * l3;
        ((float4*)g_alpha)[p] = make_float4(l0, l1, l2, l3);
        m0 = fmaxf(m0, l0); m1 = fmaxf(m1, l1);
        m2 = fmaxf(m2, l2); m3 = fmaxf(m3, l3);
    }
#pragma unroll
    for (int o = 16; o > 0; o >>= 1) {
        m0 = fmaxf(m0, __shfl_xor_sync(FULLMASK, m0, o));
        m1 = fmaxf(m1, __shfl_xor_sync(FULLMASK, m1, o));
        m2 = fmaxf(m2, __shfl_xor_sync(FULLMASK, m2, o));
        m3 = fmaxf(m3, __shfl_xor_sync(FULLMASK, m3, o));
    }
    float s0 = 0.f, s1 = 0.f, s2 = 0.f, s3 = 0.f;
    for (int p = p0 + lane; p < p1; p += 32) {
        float4 l = ((const float4*)g_alpha)[p];
        float e0 = __expf(l.x - m0), e1 = __expf(l.y - m1);
        float e2 = __expf(l.z - m2), e3 = __expf(l.w - m3);
        ((float4*)g_alpha)[p] = make_float4(e0, e1, e2, e3);
        s0 += e0; s1 += e1; s2 += e2; s3 += e3;
    }
#pragma unroll
    for (int o = 16; o > 0; o >>= 1) {
        s0 += __shfl_xor_sync(FULLMASK, s0, o);
        s1 += __shfl_xor_sync(FULLMASK, s1, o);
        s2 += __shfl_xor_sync(FULLMASK, s2, o);
        s3 += __shfl_xor_sync(FULLMASK, s3, o);
    }
    float i0 = 1.f / (s0 + 1e-16f), i1 = 1.f / (s1 + 1e-16f);
    float i2 = 1.f / (s2 + 1e-16f), i3 = 1.f / (s3 + 1e-16f);
    for (int p = p0 + lane; p < p1; p += 32) {
        float4 e = ((const float4*)g_alpha)[p];
        e.x *= i0; e.y *= i1; e.z *= i2; e.w *= i3;
        ((float4*)g_alpha)[p] = e;
        if (outAlpha) ((float4*)outAlpha)[g_csr_eid[p]] = e;
    }
}

// ---------------- layer 0 fused: logits+softmax+aggregate+bias+ELU -> h0 --------
// Warp per dst node (8 per 256-thread block). Fast path keeps alpha in registers.
__global__ void k_l0_fused(const float* __restrict__ b0) {
    int d = (blockIdx.x * 256 + threadIdx.x) >> 5;
    int lane = threadIdx.x & 31;
    if (d >= Nn) return;
    int p0 = g_rowptr[d], p1 = g_rowptr[d + 1];
    int deg = p1 - p0;
    float4 sd = ((const float4*)g_sdst)[d];
    int cc = 2 * lane, h = lane >> 3;
    float ax = 0.f, ay = 0.f;
    const __half2* xw = (const __half2*)g_xw0;

    if (deg <= 32) {
        bool act = lane < deg;
        int sidx = g_csr_src[act ? (p0 + lane) : p0];
        float4 a = ((const float4*)g_ssrc)[sidx];
        float l0 = a.x + sd.x; l0 = l0 > 0.f ? l0 : 0.2f * l0;
        float l1 = a.y + sd.y; l1 = l1 > 0.f ? l1 : 0.2f * l1;
        float l2 = a.z + sd.z; l2 = l2 > 0.f ? l2 : 0.2f * l2;
        float l3 = a.w + sd.w; l3 = l3 > 0.f ? l3 : 0.2f * l3;
        float m0 = act ? l0 : -1e30f, m1 = act ? l1 : -1e30f;
        float m2 = act ? l2 : -1e30f, m3 = act ? l3 : -1e30f;
#pragma unroll
        for (int o = 16; o > 0; o >>= 1) {
            m0 = fmaxf(m0, __shfl_xor_sync(FULLMASK, m0, o));
            m1 = fmaxf(m1, __shfl_xor_sync(FULLMASK, m1, o));
            m2 = fmaxf(m2, __shfl_xor_sync(FULLMASK, m2, o));
            m3 = fmaxf(m3, __shfl_xor_sync(FULLMASK, m3, o));
        }
        float e0 = act ? __expf(l0 - m0) : 0.f;
        float e1 = act ? __expf(l1 - m1) : 0.f;
        float e2 = act ? __expf(l2 - m2) : 0.f;
        float e3 = act ? __expf(l3 - m3) : 0.f;
        float s0 = e0, s1 = e1, s2 = e2, s3 = e3;
#pragma unroll
        for (int o = 16; o > 0; o >>= 1) {
            s0 += __shfl_xor_sync(FULLMASK, s0, o);
            s1 += __shfl_xor_sync(FULLMASK, s1, o);
            s2 += __shfl_xor_sync(FULLMASK, s2, o);
            s3 += __shfl_xor_sync(FULLMASK, s3, o);
        }
        e0 /= (s0 + 1e-16f); e1 /= (s1 + 1e-16f);
        e2 /= (s2 + 1e-16f); e3 /= (s3 + 1e-16f);
        // aggregation: broadcast per-edge (src, alpha) from lane j
        for (int j = 0; j < deg; j++) {
            int sj = __shfl_sync(FULLMASK, sidx, j);
            float a0 = __shfl_sync(FULLMASK, e0, j);
            float a1 = __shfl_sync(FULLMASK, e1, j);
            float a2 = __shfl_sync(FULLMASK, e2, j);
            float a3 = __shfl_sync(FULLMASK, e3, j);
            float al = (h == 0) ? a0 : (h == 1) ? a1 : (h == 2) ? a2 : a3;
            float2 v = __half22float2(xw[sj * 32 + lane]);
            ax += al * v.x; ay += al * v.y;
        }
    } else {
        softmax_slow(p0, p1, lane, sd, nullptr);
        for (int p = p0; p < p1; p++) {
            float al = g_alpha[4 * p + h];
            float2 v = __half22float2(xw[g_csr_src[p] * 32 + lane]);
            ax += al * v.x; ay += al * v.y;
        }
    }
    float v0 = ax + b0[cc];
    float v1 = ay + b0[cc + 1];
    v0 = (v0 > 0.f) ? v0 : expm1f(v0);
    v1 = (v1 > 0.f) ? v1 : expm1f(v1);
    g_h0[d * 64 + cc] = v0;
    g_h0[d * 64 + cc + 1] = v1;
}

// ---------------- layer 1 fused: softmax+aggregate+mean+ELU+LN -> g_ht[t] -------
// Block of 128 per dst node. Warp 0: softmax -> smem; all warps: 256-col gather.
__global__ void k_l1_fused(const float* __restrict__ b1, const float* __restrict__ ln_g,
                           const float* __restrict__ ln_b, int t,
                           float* __restrict__ outAlpha) {
    int d = blockIdx.x;
    int tid = threadIdx.x;  // 128
    int lane = tid & 31;
    int h = tid >> 5;
    int p0 = g_rowptr[d], p1 = g_rowptr[d + 1];
    int deg = p1 - p0;
    __shared__ float4 salpha[32];
    __shared__ int ssidx[32];

    if (tid < 32) {
        float4 sdv = ((const float4*)g_sdst)[d];
        if (deg <= 32) {
            bool act = lane < deg;
            int sidx = g_csr_src[act ? (p0 + lane) : p0];
            float4 a = ((const float4*)g_ssrc)[sidx];
            float l0 = a.x + sdv.x; l0 = l0 > 0.f ? l0 : 0.2f * l0;
            float l1 = a.y + sdv.y; l1 = l1 > 0.f ? l1 : 0.2f * l1;
            float l2 = a.z + sdv.z; l2 = l2 > 0.f ? l2 : 0.2f * l2;
            float l3 = a.w + sdv.w; l3 = l3 > 0.f ? l3 : 0.2f * l3;
            float m0 = act ? l0 : -1e30f, m1 = act ? l1 : -1e30f;
            float m2 = act ? l2 : -1e30f, m3 = act ? l3 : -1e30f;
#pragma unroll
            for (int o = 16; o > 0; o >>= 1) {
                m0 = fmaxf(m0, __shfl_xor_sync(FULLMASK, m0, o));
                m1 = fmaxf(m1, __shfl_xor_sync(FULLMASK, m1, o));
                m2 = fmaxf(m2, __shfl_xor_sync(FULLMASK, m2, o));
                m3 = fmaxf(m3, __shfl_xor_sync(FULLMASK, m3, o));
            }
            float e0 = act ? __expf(l0 - m0) : 0.f;
            float e1 = act ? __expf(l1 - m1) : 0.f;
            float e2 = act ? __expf(l2 - m2) : 0.f;
            float e3 = act ? __expf(l3 - m3) : 0.f;
            float s0 = e0, s1 = e1, s2 = e2, s3 = e3;
#pragma unroll
            for (int o = 16; o > 0; o >>= 1) {
                s0 += __shfl_xor_sync(FULLMASK, s0, o);
                s1 += __shfl_xor_sync(FULLMASK, s1, o);
                s2 += __shfl_xor_sync(FULLMASK, s2, o);
                s3 += __shfl_xor_sync(FULLMASK, s3, o);
            }
            float4 e = make_float4(e0 / (s0 + 1e-16f), e1 / (s1 + 1e-16f),
                                   e2 / (s2 + 1e-16f), e3 / (s3 + 1e-16f));
            salpha[lane] = e;
            ssidx[lane] = sidx;
            if (act && outAlpha) ((float4*)outAlpha)[g_csr_eid[p0 + lane]] = e;
        } else {
            softmax_slow(p0, p1, lane, sdv, outAlpha);
        }
    }
    __syncthreads();

    const __half2* xw = (const __half2*)g_xw1;
    float ax = 0.f, ay = 0.f;
    if (deg <= 32) {
        for (int j = 0; j < deg; j++) {
            float al = ((const float*)&salpha[j])[h];
            int sj = ssidx[j];
            float2 v = __half22float2(xw[(size_t)sj * 128 + tid]);
            ax += al * v.x; ay += al * v.y;
        }
    } else {
        for (int p = p0; p < p1; p++) {
            float al = g_alpha[4 * p + h];
            float2 v = __half22float2(xw[(size_t)g_csr_src[p] * 128 + tid]);
            ax += al * v.x; ay += al * v.y;
        }
    }
    __shared__ float2 sh2[128];
    sh2[tid] = make_float2(ax, ay);
    __syncthreads();
    if (tid < 32) {
        float2 a0 = sh2[tid], a1 = sh2[tid + 32], a2 = sh2[tid + 64], a3 = sh2[tid + 96];
        int cc = 2 * tid;
        float v0 = (a0.x + a1.x + a2.x + a3.x) * 0.25f + b1[cc];
        float v1 = (a0.y + a1.y + a2.y + a3.y) * 0.25f + b1[cc + 1];
        v0 = (v0 > 0.f) ? v0 : expm1f(v0);
        v1 = (v1 > 0.f) ? v1 : expm1f(v1);
        float s = v0 + v1, q = v0 * v0 + v1 * v1;
#pragma unroll
        for (int o = 16; o > 0; o >>= 1) {
            s += __shfl_xor_sync(FULLMASK, s, o);
            q += __shfl_xor_sync(FULLMASK, q, o);
        }
        float mean = s * (1.f / 64.f);
        float var = q * (1.f / 64.f) - mean * mean;
        float is = rsqrtf(var + 1e-5f);
        float* ht = g_ht + (size_t)t * Nn * 64;
        ht[d * 64 + cc]     = (v0 - mean) * is * ln_g[cc]     + ln_b[cc];
        ht[d * 64 + cc + 1] = (v1 - mean) * is * ln_g[cc + 1] + ln_b[cc + 1];
    }
}

// ---------------- GRU input-gate GEMM over all (t,n) rows -----------------------
__global__ void k_gi_all(const float* __restrict__ b_ih) {
    __shared__ __align__(16) float sx[32][64];
    int tid = threadIdx.x;  // 192
    int r0 = blockIdx.x * 32;
    for (int i = tid; i < 32 * 64; i += 192) {
        int r = i >> 6, c = i & 63;
        sx[r][c] = g_ht[(size_t)(r0 + r) * 64 + c];
    }
    float w[64];
#pragma unroll
    for (int j = 0; j < 64; j++) w[j] = g_Wt_ih[j * 192 + tid];
    __syncthreads();
    float acc[32];
#pragma unroll
    for (int r = 0; r < 32; r++) acc[r] = 0.f;
#pragma unroll 8
    for (int j4 = 0; j4 < 16; j4++) {
#pragma unroll
        for (int r = 0; r < 32; r++) {
            float4 xv = *(const float4*)&sx[r][4 * j4];
            acc[r] += xv.x * w[4 * j4] + xv.y * w[4 * j4 + 1]
                    + xv.z * w[4 * j4 + 2] + xv.w * w[4 * j4 + 3];
        }
    }
    float b = b_ih[tid];
#pragma unroll
    for (int r = 0; r < 32; r++)
        g_gi[(size_t)(r0 + r) * 192 + tid] = acc[r] + b;
}

// ---------------- GRU recurrence: single kernel over all timesteps --------------
__global__ void k_gru_all(const float* __restrict__ b_hh, float* __restrict__ outp) {
    __shared__ __align__(16) float shh[16][64];
    __shared__ float gh[16][192];
    int tid = threadIdx.x;  // 192
    int n0 = blockIdx.x * 16;
    float w[64];
#pragma unroll
    for (int j = 0; j < 64; j++) w[j] = g_Wt_hh[j * 192 + tid];
    float bh = b_hh[tid];
    for (int i = tid; i < 16 * 64; i += 192) shh[i >> 6][i & 63] = 0.f;
    __syncthreads();
    for (int t = 0; t < Tt; t++) {
        float ah[16];
#pragma unroll
        for (int r = 0; r < 16; r++) ah[r] = 0.f;
#pragma unroll 8
        for (int j4 = 0; j4 < 16; j4++) {
#pragma unroll
            for (int r = 0; r < 16; r++) {
                float4 hv = *(const float4*)&shh[r][4 * j4];
                ah[r] += hv.x * w[4 * j4] + hv.y * w[4 * j4 + 1]
                       + hv.z * w[4 * j4 + 2] + hv.w * w[4 * j4 + 3];
            }
        }
#pragma unroll
        for (int r = 0; r < 16; r++) gh[r][tid] = ah[r] + bh;
        __syncthreads();
        const float* gi = g_gi + ((size_t)t * Nn + n0) * 192;
        for (int i = tid; i < 16 * 64; i += 192) {
            int r = i >> 6, kk = i & 63;
            float ir = gi[r * 192 + kk];
            float iz = gi[r * 192 + 64 + kk];
            float ig = gi[r * 192 + 128 + kk];
            float hr = gh[r][kk], hz = gh[r][64 + kk], hg = gh[r][128 + kk];
            float rr = 1.f / (1.f + __expf(-(ir + hr)));
            float zz = 1.f / (1.f + __expf(-(iz + hz)));
            float gg = tanhf(ig + rr * hg);
            float hn = (1.f - zz) * gg + zz * shh[r][kk];
            shh[r][kk] = hn;
            if (t == Tt - 1) outp[(n0 + r) * 64 + kk] = hn;
        }
        __syncthreads();
    }
}

// ---------------- output writers ------------------------------------------------
__global__ void k_write_edges(const void* __restrict__ ei, float* __restrict__ out,
                              int mode) {
    int is64 = block_detect64(ei);
    int e = blockIdx.x * 256 + threadIdx.x;
    if (e >= EP) return;
    int s = (e < Ee) ? edge_val(ei, e, is64) : (e - Ee);
    int d = (e < Ee) ? edge_val(ei, Ee + e, is64) : (e - Ee);
    size_t base = (size_t)Nn * 64 + (size_t)EP * 4;
    if (mode == 1) {
        long long* p = (long long*)(out + base);
        p[e] = (long long)s;
        p[EP + e] = (long long)d;
    } else {
        out[base + e] = (float)s;
        out[base + EP + e] = (float)d;
    }
}

// ---------------- host launch ---------------------------------------------------
extern "C" void kernel_launch(void* const* d_in, const int* in_sizes, int n_in,
                              void* d_out, int out_size) {
    const float* x      = (const float*)d_in[0];
    const void*  ei     = (const void*)d_in[1];
    const float* W0     = (const float*)d_in[2];
    const float* a_src0 = (const float*)d_in[3];
    const float* a_dst0 = (const float*)d_in[4];
    const float* b0     = (const float*)d_in[5];
    const float* W1     = (const float*)d_in[6];
    const float* a_src1 = (const float*)d_in[7];
    const float* a_dst1 = (const float*)d_in[8];
    const float* b1     = (const float*)d_in[9];
    const float* ln_g   = (const float*)d_in[10];
    const float* ln_b   = (const float*)d_in[11];
    const float* W_ih   = (const float*)d_in[12];
    const float* W_hh   = (const float*)d_in[13];
    const float* b_ih   = (const float*)d_in[14];
    const float* b_hh   = (const float*)d_in[15];

    float* out = (float*)d_out;

    const int EB   = (EP + 255) / 256;
    const int NB32 = (Nn + 31) / 32;   // 313
    const int WPB  = (Nn * 32 + 255) / 256;  // 1250 warp-per-node blocks

    k_init<<<(192 * 64 + 255) / 256, 256>>>(W_ih, W_hh);
    k_count<<<EB, 256>>>(ei);
    k_scan<<<1, 1024>>>();
    k_scatter<<<EB, 256>>>(ei);

    bool haveAlpha = (long long)out_size >= (long long)Nn * 64 + (long long)EP * 4;

    for (int t = 0; t < Tt; t++) {
        k_l0_gemm<<<NB32, 256>>>(x, W0, a_src0, a_dst0, t);
        k_l0_fused<<<WPB, 256>>>(b0);
        k_l1_gemm<<<NB32, 256>>>(W1, a_src1, a_dst1);
        float* oa = (t == Tt - 1 && haveAlpha) ? (out + (size_t)Nn * 64) : nullptr;
        k_l1_fused<<<Nn, 128>>>(b1, ln_g, ln_b, t, oa);
    }
    // GRU: wide input-gate GEMM over all (t,n), then register-weight recurrence.
    k_gi_all<<<Nn * Tt / 32, 192>>>(b_ih);
    k_gru_all<<<Nn / 16, 192>>>(b_hh, out);

    long long tail = (long long)out_size - ((long long)Nn * 64 + (long long)EP * 4);
    if (tail >= 4LL * EP) {
        k_write_edges<<<EB, 256>>>(ei, out, 1);
    } else if (tail >= 2LL * EP) {
        k_write_edges<<<EB, 256>>>(ei, out, 0);
    }
}

// round 16
// speedup vs baseline: 1.2015x; 1.2015x over previous
#include <cuda_runtime.h>
#include <cuda_fp16.h>

// Problem constants (fixed by the dataset)
#define Nn 10000
#define Tt 6
#define Ff 64
#define Ee 160000
#define EP 170000   // Ee + Nn self loops
#define FULLMASK 0xffffffffu

// ---------------- scratch (device globals; no allocations allowed) -------------
__device__ __align__(16) __half g_xw0[Tt * Nn * 64];      // layer0 features, per t
__device__ __align__(16) float  g_h0[Nn * 64];
__device__ __align__(16) __half g_xw1[Nn * 256];          // layer1 features (per-t reuse)
// head-sum slices: t=0..5 for layer0 per-t, slice Tt for layer1 scratch
__device__ __align__(16) float  g_ssrc[(Tt + 1) * Nn * 4];
__device__ __align__(16) float  g_sdst[(Tt + 1) * Nn * 4];
__device__ __align__(16) float  g_lg[EP * 4];
__device__ __align__(16) float  g_alpha[EP * 4];
__device__ __align__(16) float  g_ht[Tt * Nn * 64];
__device__ __align__(16) float  g_gi[(size_t)Tt * Nn * 192];
__device__ float g_Wt_ih[64 * 192];
__device__ float g_Wt_hh[64 * 192];
__device__ int g_deg[Nn];
__device__ int g_rowptr[Nn + 1];
__device__ int g_cursor[Nn];
__device__ int g_csr_src[EP];
__device__ int g_csr_dst[EP];
__device__ int g_csr_eid[EP];

// ---------------- inline edge dtype detect (one thread/block, shared flag) ------
__device__ __forceinline__ int block_detect64(const void* ei) {
    __shared__ int sIs64;
    if (threadIdx.x == 0) {
        const int* w = (const int*)ei;
        int zeros = 0;
#pragma unroll
        for (int i = 0; i < 16; i++)
            if (w[2 * i + 1] == 0) zeros++;
        sIs64 = (zeros > 8) ? 1 : 0;
    }
    __syncthreads();
    return sIs64;
}

__device__ __forceinline__ int edge_val(const void* ei, int idx, int is64) {
    if (is64) return (int)((const long long*)ei)[idx];
    return ((const int*)ei)[idx];
}

// ---------------- init: zero deg, transpose GRU weights -------------------------
__global__ void k_init(const float* __restrict__ W_ih, const float* __restrict__ W_hh) {
    int i = blockIdx.x * 256 + threadIdx.x;
    if (i < Nn) g_deg[i] = 0;
    if (i < 192 * 64) {
        int kk = i / 64, j = i % 64;
        g_Wt_ih[j * 192 + kk] = W_ih[i];
        g_Wt_hh[j * 192 + kk] = W_hh[i];
    }
}

// ---------------- CSR build (dst-major) -----------------------------------------
__global__ void k_count(const void* __restrict__ ei) {
    int is64 = block_detect64(ei);
    int e = blockIdx.x * 256 + threadIdx.x;
    if (e >= EP) return;
    int d = (e < Ee) ? edge_val(ei, Ee + e, is64) : (e - Ee);
    atomicAdd(&g_deg[d], 1);
}

__global__ void k_scan() {
    __shared__ int wsum[32];
    int tid = threadIdx.x;
    const int IT = 10;
    int base = tid * IT;
    int vals[IT];
    int s = 0;
#pragma unroll
    for (int i = 0; i < IT; i++) {
        int idx = base + i;
        int v = (idx < Nn) ? g_deg[idx] : 0;
        vals[i] = s;
        s += v;
    }
    int lane = tid & 31, w = tid >> 5;
    int inc = s;
    for (int o = 1; o < 32; o <<= 1) {
        int y = __shfl_up_sync(FULLMASK, inc, o);
        if (lane >= o) inc += y;
    }
    if (lane == 31) wsum[w] = inc;
    __syncthreads();
    if (w == 0) {
        int v = wsum[lane];
        for (int o = 1; o < 32; o <<= 1) {
            int y = __shfl_up_sync(FULLMASK, v, o);
            if (lane >= o) v += y;
        }
        wsum[lane] = v;
    }
    __syncthreads();
    int excl = inc - s + ((w > 0) ? wsum[w - 1] : 0);
#pragma unroll
    for (int i = 0; i < IT; i++) {
        int idx = base + i;
        if (idx < Nn) {
            g_rowptr[idx] = excl + vals[i];
            g_cursor[idx] = excl + vals[i];
        }
    }
    if (tid == 1023) g_rowptr[Nn] = wsum[31];
}

__global__ void k_scatter(const void* __restrict__ ei) {
    int is64 = block_detect64(ei);
    int e = blockIdx.x * 256 + threadIdx.x;
    if (e >= EP) return;
    int s = (e < Ee) ? edge_val(ei, e, is64) : (e - Ee);
    int d = (e < Ee) ? edge_val(ei, Ee + e, is64) : (e - Ee);
    int p = atomicAdd(&g_cursor[d], 1);
    g_csr_src[p] = s;
    g_csr_dst[p] = d;
    g_csr_eid[p] = e;
}

// ---------------- GAT layer 0 GEMM + head sums, ALL timesteps (grid.y = t) ------
__global__ void k_l0_gemm_all(const float* __restrict__ x, const float* __restrict__ W0,
                              const float* __restrict__ a_src, const float* __restrict__ a_dst) {
    __shared__ float sW[64 * 64];
    __shared__ __align__(16) float sx[32][64];
    int tid = threadIdx.x;
    int t = blockIdx.y;
    int n0 = blockIdx.x * 32;
    for (int i = tid; i < 64 * 64; i += 256) sW[i] = W0[i];
    for (int i = tid; i < 32 * 64; i += 256) {
        int r = i >> 6, c = i & 63;
        int n = n0 + r;
        sx[r][c] = (n < Nn) ? x[(size_t)n * (Tt * Ff) + t * Ff + c] : 0.f;
    }
    __syncthreads();
    int r4 = tid >> 6, c = tid & 63;
    float acc[8];
#pragma unroll
    for (int q = 0; q < 8; q++) acc[q] = 0.f;
#pragma unroll
    for (int j4 = 0; j4 < 16; j4++) {
        float w0 = sW[(4 * j4 + 0) * 64 + c];
        float w1 = sW[(4 * j4 + 1) * 64 + c];
        float w2 = sW[(4 * j4 + 2) * 64 + c];
        float w3 = sW[(4 * j4 + 3) * 64 + c];
#pragma unroll
        for (int q = 0; q < 8; q++) {
            float4 xv = *(const float4*)&sx[r4 + 4 * q][4 * j4];
            acc[q] += xv.x * w0 + xv.y * w1 + xv.z * w2 + xv.w * w3;
        }
    }
    float as = a_src[c], ad = a_dst[c];
    __half* xw0 = g_xw0 + (size_t)t * Nn * 64;
    float* ssrc = g_ssrc + (size_t)t * Nn * 4;
    float* sdst = g_sdst + (size_t)t * Nn * 4;
#pragma unroll
    for (int q = 0; q < 8; q++) {
        int row = n0 + r4 + 4 * q;
        float pr = acc[q] * as, pd = acc[q] * ad;
#pragma unroll
        for (int o = 8; o > 0; o >>= 1) {
            pr += __shfl_down_sync(FULLMASK, pr, o);
            pd += __shfl_down_sync(FULLMASK, pd, o);
        }
        if (row < Nn) {
            xw0[row * 64 + c] = __float2half(acc[q]);
            if ((c & 15) == 0) {
                ssrc[row * 4 + (c >> 4)] = pr;
                sdst[row * 4 + (c >> 4)] = pd;
            }
        }
    }
}

// ---------------- GAT layer 1 GEMM + head sums (32 rows/block) ------------------
// Writes head sums into slice Tt of g_ssrc/g_sdst.
__global__ void k_l1_gemm(const float* __restrict__ W1, const float* __restrict__ a_src,
                          const float* __restrict__ a_dst) {
    __shared__ __align__(16) float sx[32][64];
    __shared__ float rs[32][8], rd[32][8];
    int tid = threadIdx.x;  // 256
    int n0 = blockIdx.x * 32;
    for (int i = tid; i < 32 * 64; i += 256) {
        int r = i >> 6, c = i & 63;
        int n = n0 + r;
        sx[r][c] = (n < Nn) ? g_h0[n * 64 + c] : 0.f;
    }
    __syncthreads();
    float acc[32];
#pragma unroll
    for (int r = 0; r < 32; r++) acc[r] = 0.f;
#pragma unroll 4
    for (int j4 = 0; j4 < 16; j4++) {
        float w0 = W1[(4 * j4 + 0) * 256 + tid];
        float w1 = W1[(4 * j4 + 1) * 256 + tid];
        float w2 = W1[(4 * j4 + 2) * 256 + tid];
        float w3 = W1[(4 * j4 + 3) * 256 + tid];
#pragma unroll
        for (int r = 0; r < 32; r++) {
            float4 xv = *(const float4*)&sx[r][4 * j4];
            acc[r] += xv.x * w0 + xv.y * w1 + xv.z * w2 + xv.w * w3;
        }
    }
    float as = a_src[tid], ad = a_dst[tid];
    int lane = tid & 31, w8 = tid >> 5;
#pragma unroll
    for (int r = 0; r < 32; r++) {
        int n = n0 + r;
        if (n < Nn) g_xw1[(size_t)n * 256 + tid] = __float2half(acc[r]);
        float pr = acc[r] * as, pd = acc[r] * ad;
#pragma unroll
        for (int o = 16; o > 0; o >>= 1) {
            pr += __shfl_down_sync(FULLMASK, pr, o);
            pd += __shfl_down_sync(FULLMASK, pd, o);
        }
        if (lane == 0) { rs[r][w8] = pr; rd[r][w8] = pd; }
    }
    __syncthreads();
    if (tid < 128) {
        int r = tid >> 2, h = tid & 3;
        int n = n0 + r;
        if (n < Nn) {
            g_ssrc[(size_t)Tt * Nn * 4 + n * 4 + h] = rs[r][2 * h] + rs[r][2 * h + 1];
            g_sdst[(size_t)Tt * Nn * 4 + n * 4 + h] = rd[r][2 * h] + rd[r][2 * h + 1];
        }
    }
}

// ---------------- fused edge-logit + segment softmax (warp per dst node) --------
// slice selects the head-sum buffers (t for layer0, Tt for layer1).
__global__ void k_softmax_fused(int slice, float* __restrict__ outAlpha) {
    int gw = (blockIdx.x * 256 + threadIdx.x) >> 5;
    int lane = threadIdx.x & 31;
    if (gw >= Nn) return;
    const float4* ssrc4 = (const float4*)g_ssrc + (size_t)slice * Nn;
    const float4* sdst4 = (const float4*)g_sdst + (size_t)slice * Nn;
    int p0 = g_rowptr[gw], p1 = g_rowptr[gw + 1];
    int deg = p1 - p0;
    float4 sd = sdst4[gw];

    if (deg <= 32) {
        int p = p0 + lane;
        bool act = lane < deg;
        int sidx = g_csr_src[act ? p : p0];
        float4 a = ssrc4[sidx];
        float l0 = a.x + sd.x; l0 = l0 > 0.f ? l0 : 0.2f * l0;
        float l1 = a.y + sd.y; l1 = l1 > 0.f ? l1 : 0.2f * l1;
        float l2 = a.z + sd.z; l2 = l2 > 0.f ? l2 : 0.2f * l2;
        float l3 = a.w + sd.w; l3 = l3 > 0.f ? l3 : 0.2f * l3;
        float m0 = act ? l0 : -1e30f, m1 = act ? l1 : -1e30f;
        float m2 = act ? l2 : -1e30f, m3 = act ? l3 : -1e30f;
#pragma unroll
        for (int o = 16; o > 0; o >>= 1) {
            m0 = fmaxf(m0, __shfl_xor_sync(FULLMASK, m0, o));
            m1 = fmaxf(m1, __shfl_xor_sync(FULLMASK, m1, o));
            m2 = fmaxf(m2, __shfl_xor_sync(FULLMASK, m2, o));
            m3 = fmaxf(m3, __shfl_xor_sync(FULLMASK, m3, o));
        }
        float e0 = act ? __expf(l0 - m0) : 0.f;
        float e1 = act ? __expf(l1 - m1) : 0.f;
        float e2 = act ? __expf(l2 - m2) : 0.f;
        float e3 = act ? __expf(l3 - m3) : 0.f;
        float s0 = e0, s1 = e1, s2 = e2, s3 = e3;
#pragma unroll
        for (int o = 16; o > 0; o >>= 1) {
            s0 += __shfl_xor_sync(FULLMASK, s0, o);
            s1 += __shfl_xor_sync(FULLMASK, s1, o);
            s2 += __shfl_xor_sync(FULLMASK, s2, o);
            s3 += __shfl_xor_sync(FULLMASK, s3, o);
        }
        if (act) {
            float4 e = make_float4(e0 / (s0 + 1e-16f), e1 / (s1 + 1e-16f),
                                   e2 / (s2 + 1e-16f), e3 / (s3 + 1e-16f));
            ((float4*)g_alpha)[p] = e;
            if (outAlpha) ((float4*)outAlpha)[g_csr_eid[p]] = e;
        }
        return;
    }

    float m0 = -1e30f, m1 = -1e30f, m2 = -1e30f, m3 = -1e30f;
    for (int p = p0 + lane; p < p1; p += 32) {
        float4 a = ssrc4[g_csr_src[p]];
        float l0 = a.x + sd.x; l0 = l0 > 0.f ? l0 : 0.2f * l0;
        float l1 = a.y + sd.y; l1 = l1 > 0.f ? l1 : 0.2f * l1;
        float l2 = a.z + sd.z; l2 = l2 > 0.f ? l2 : 0.2f * l2;
        float l3 = a.w + sd.w; l3 = l3 > 0.f ? l3 : 0.2f * l3;
        ((float4*)g_lg)[p] = make_float4(l0, l1, l2, l3);
        m0 = fmaxf(m0, l0); m1 = fmaxf(m1, l1);
        m2 = fmaxf(m2, l2); m3 = fmaxf(m3, l3);
    }
#pragma unroll
    for (int o = 16; o > 0; o >>= 1) {
        m0 = fmaxf(m0, __shfl_xor_sync(FULLMASK, m0, o));
        m1 = fmaxf(m1, __shfl_xor_sync(FULLMASK, m1, o));
        m2 = fmaxf(m2, __shfl_xor_sync(FULLMASK, m2, o));
        m3 = fmaxf(m3, __shfl_xor_sync(FULLMASK, m3, o));
    }
    float s0 = 0.f, s1 = 0.f, s2 = 0.f, s3 = 0.f;
    for (int p = p0 + lane; p < p1; p += 32) {
        float4 l = ((const float4*)g_lg)[p];
        float e0 = __expf(l.x - m0), e1 = __expf(l.y - m1);
        float e2 = __expf(l.z - m2), e3 = __expf(l.w - m3);
        ((float4*)g_alpha)[p] = make_float4(e0, e1, e2, e3);
        s0 += e0; s1 += e1; s2 += e2; s3 += e3;
    }
#pragma unroll
    for (int o = 16; o > 0; o >>= 1) {
        s0 += __shfl_xor_sync(FULLMASK, s0, o);
        s1 += __shfl_xor_sync(FULLMASK, s1, o);
        s2 += __shfl_xor_sync(FULLMASK, s2, o);
        s3 += __shfl_xor_sync(FULLMASK, s3, o);
    }
    float i0 = 1.f / (s0 + 1e-16f), i1 = 1.f / (s1 + 1e-16f);
    float i2 = 1.f / (s2 + 1e-16f), i3 = 1.f / (s3 + 1e-16f);
    for (int p = p0 + lane; p < p1; p += 32) {
        float4 e = ((const float4*)g_alpha)[p];
        e.x *= i0; e.y *= i1; e.z *= i2; e.w *= i3;
        ((float4*)g_alpha)[p] = e;
        if (outAlpha) ((float4*)outAlpha)[g_csr_eid[p]] = e;
    }
}

// ---------------- layer-0 aggregation + bias + elu -> h0 ------------------------
// 256 threads = 8 nodes x 32 lanes; lane owns column pair (2*lane, 2*lane+1).
__global__ void k_aggr0(const float* __restrict__ b0, int t) {
    int d = blockIdx.x * 8 + (threadIdx.x >> 5);
    int lane = threadIdx.x & 31;
    int h = lane >> 3;
    int p0 = g_rowptr[d], p1 = g_rowptr[d + 1];
    const __half2* xw = (const __half2*)(g_xw0 + (size_t)t * Nn * 64);
    float ax = 0.f, ay = 0.f;
    int p = p0;
    for (; p + 4 <= p1; p += 4) {
        int s0 = g_csr_src[p], s1 = g_csr_src[p + 1];
        int s2 = g_csr_src[p + 2], s3 = g_csr_src[p + 3];
        float a0 = g_alpha[4 * p + h],       a1 = g_alpha[4 * (p + 1) + h];
        float a2 = g_alpha[4 * (p + 2) + h], a3 = g_alpha[4 * (p + 3) + h];
        float2 v0 = __half22float2(xw[s0 * 32 + lane]);
        float2 v1 = __half22float2(xw[s1 * 32 + lane]);
        float2 v2 = __half22float2(xw[s2 * 32 + lane]);
        float2 v3 = __half22float2(xw[s3 * 32 + lane]);
        ax += a0 * v0.x + a1 * v1.x + a2 * v2.x + a3 * v3.x;
        ay += a0 * v0.y + a1 * v1.y + a2 * v2.y + a3 * v3.y;
    }
    for (; p < p1; p++) {
        float a = g_alpha[4 * p + h];
        float2 v = __half22float2(xw[g_csr_src[p] * 32 + lane]);
        ax += a * v.x; ay += a * v.y;
    }
    int cc = 2 * lane;
    float v0 = ax + b0[cc];
    float v1 = ay + b0[cc + 1];
    v0 = (v0 > 0.f) ? v0 : expm1f(v0);
    v1 = (v1 > 0.f) ? v1 : expm1f(v1);
    g_h0[d * 64 + cc] = v0;
    g_h0[d * 64 + cc + 1] = v1;
}

// ---------------- layer-1 aggregation + head-mean + elu + LN -> g_ht[t] ---------
// 128 threads per node; thread owns column pair (2*tid, 2*tid+1); head = tid>>5.
__global__ void k_aggr1(const float* __restrict__ b1, const float* __restrict__ ln_g,
                        const float* __restrict__ ln_b, int t) {
    int d = blockIdx.x;
    int tid = threadIdx.x;  // 128
    int h = tid >> 5;
    int p0 = g_rowptr[d], p1 = g_rowptr[d + 1];
    const __half2* xw = (const __half2*)g_xw1;
    float ax = 0.f, ay = 0.f;
    int p = p0;
    for (; p + 4 <= p1; p += 4) {
        int s0 = g_csr_src[p], s1 = g_csr_src[p + 1];
        int s2 = g_csr_src[p + 2], s3 = g_csr_src[p + 3];
        float a0 = g_alpha[4 * p + h],       a1 = g_alpha[4 * (p + 1) + h];
        float a2 = g_alpha[4 * (p + 2) + h], a3 = g_alpha[4 * (p + 3) + h];
        float2 v0 = __half22float2(xw[(size_t)s0 * 128 + tid]);
        float2 v1 = __half22float2(xw[(size_t)s1 * 128 + tid]);
        float2 v2 = __half22float2(xw[(size_t)s2 * 128 + tid]);
        float2 v3 = __half22float2(xw[(size_t)s3 * 128 + tid]);
        ax += a0 * v0.x + a1 * v1.x + a2 * v2.x + a3 * v3.x;
        ay += a0 * v0.y + a1 * v1.y + a2 * v2.y + a3 * v3.y;
    }
    for (; p < p1; p++) {
        float a = g_alpha[4 * p + h];
        float2 v = __half22float2(xw[(size_t)g_csr_src[p] * 128 + tid]);
        ax += a * v.x; ay += a * v.y;
    }
    __shared__ float2 sh2[128];
    sh2[tid] = make_float2(ax, ay);
    __syncthreads();
    if (tid < 32) {
        float2 a0 = sh2[tid], a1 = sh2[tid + 32], a2 = sh2[tid + 64], a3 = sh2[tid + 96];
        int cc = 2 * tid;
        float v0 = (a0.x + a1.x + a2.x + a3.x) * 0.25f + b1[cc];
        float v1 = (a0.y + a1.y + a2.y + a3.y) * 0.25f + b1[cc + 1];
        v0 = (v0 > 0.f) ? v0 : expm1f(v0);
        v1 = (v1 > 0.f) ? v1 : expm1f(v1);
        float s = v0 + v1, q = v0 * v0 + v1 * v1;
#pragma unroll
        for (int o = 16; o > 0; o >>= 1) {
            s += __shfl_xor_sync(FULLMASK, s, o);
            q += __shfl_xor_sync(FULLMASK, q, o);
        }
        float mean = s * (1.f / 64.f);
        float var = q * (1.f / 64.f) - mean * mean;
        float is = rsqrtf(var + 1e-5f);
        float* ht = g_ht + (size_t)t * Nn * 64;
        ht[d * 64 + cc]     = (v0 - mean) * is * ln_g[cc]     + ln_b[cc];
        ht[d * 64 + cc + 1] = (v1 - mean) * is * ln_g[cc + 1] + ln_b[cc + 1];
    }
}

// ---------------- GRU input-gate GEMM over all (t,n) rows -----------------------
__global__ void k_gi_all(const float* __restrict__ b_ih) {
    __shared__ __align__(16) float sx[32][64];
    int tid = threadIdx.x;  // 192
    int r0 = blockIdx.x * 32;
    for (int i = tid; i < 32 * 64; i += 192) {
        int r = i >> 6, c = i & 63;
        sx[r][c] = g_ht[(size_t)(r0 + r) * 64 + c];
    }
    float w[64];
#pragma unroll
    for (int j = 0; j < 64; j++) w[j] = g_Wt_ih[j * 192 + tid];
    __syncthreads();
    float acc[32];
#pragma unroll
    for (int r = 0; r < 32; r++) acc[r] = 0.f;
#pragma unroll 8
    for (int j4 = 0; j4 < 16; j4++) {
#pragma unroll
        for (int r = 0; r < 32; r++) {
            float4 xv = *(const float4*)&sx[r][4 * j4];
            acc[r] += xv.x * w[4 * j4] + xv.y * w[4 * j4 + 1]
                    + xv.z * w[4 * j4 + 2] + xv.w * w[4 * j4 + 3];
        }
    }
    float b = b_ih[tid];
#pragma unroll
    for (int r = 0; r < 32; r++)
        g_gi[(size_t)(r0 + r) * 192 + tid] = acc[r] + b;
}

// ---------------- GRU recurrence: single kernel over all timesteps --------------
__global__ void k_gru_all(const float* __restrict__ b_hh, float* __restrict__ outp) {
    __shared__ __align__(16) float shh[16][64];
    __shared__ float gh[16][192];
    int tid = threadIdx.x;  // 192
    int n0 = blockIdx.x * 16;
    float w[64];
#pragma unroll
    for (int j = 0; j < 64; j++) w[j] = g_Wt_hh[j * 192 + tid];
    float bh = b_hh[tid];
    for (int i = tid; i < 16 * 64; i += 192) shh[i >> 6][i & 63] = 0.f;
    __syncthreads();
    for (int t = 0; t < Tt; t++) {
        float ah[16];
#pragma unroll
        for (int r = 0; r < 16; r++) ah[r] = 0.f;
#pragma unroll 8
        for (int j4 = 0; j4 < 16; j4++) {
#pragma unroll
            for (int r = 0; r < 16; r++) {
                float4 hv = *(const float4*)&shh[r][4 * j4];
                ah[r] += hv.x * w[4 * j4] + hv.y * w[4 * j4 + 1]
                       + hv.z * w[4 * j4 + 2] + hv.w * w[4 * j4 + 3];
            }
        }
#pragma unroll
        for (int r = 0; r < 16; r++) gh[r][tid] = ah[r] + bh;
        __syncthreads();
        const float* gi = g_gi + ((size_t)t * Nn + n0) * 192;
        for (int i = tid; i < 16 * 64; i += 192) {
            int r = i >> 6, kk = i & 63;
            float ir = gi[r * 192 + kk];
            float iz = gi[r * 192 + 64 + kk];
            float ig = gi[r * 192 + 128 + kk];
            float hr = gh[r][kk], hz = gh[r][64 + kk], hg = gh[r][128 + kk];
            float rr = 1.f / (1.f + __expf(-(ir + hr)));
            float zz = 1.f / (1.f + __expf(-(iz + hz)));
            float gg = tanhf(ig + rr * hg);
            float hn = (1.f - zz) * gg + zz * shh[r][kk];
            shh[r][kk] = hn;
            if (t == Tt - 1) outp[(n0 + r) * 64 + kk] = hn;
        }
        __syncthreads();
    }
}

// ---------------- output writers ------------------------------------------------
__global__ void k_write_edges(const void* __restrict__ ei, float* __restrict__ out,
                              int mode) {
    int is64 = block_detect64(ei);
    int e = blockIdx.x * 256 + threadIdx.x;
    if (e >= EP) return;
    int s = (e < Ee) ? edge_val(ei, e, is64) : (e - Ee);
    int d = (e < Ee) ? edge_val(ei, Ee + e, is64) : (e - Ee);
    size_t base = (size_t)Nn * 64 + (size_t)EP * 4;
    if (mode == 1) {
        long long* p = (long long*)(out + base);
        p[e] = (long long)s;
        p[EP + e] = (long long)d;
    } else {
        out[base + e] = (float)s;
        out[base + EP + e] = (float)d;
    }
}

// ---------------- host launch ---------------------------------------------------
extern "C" void kernel_launch(void* const* d_in, const int* in_sizes, int n_in,
                              void* d_out, int out_size) {
    const float* x      = (const float*)d_in[0];
    const void*  ei     = (const void*)d_in[1];
    const float* W0     = (const float*)d_in[2];
    const float* a_src0 = (const float*)d_in[3];
    const float* a_dst0 = (const float*)d_in[4];
    const float* b0     = (const float*)d_in[5];
    const float* W1     = (const float*)d_in[6];
    const float* a_src1 = (const float*)d_in[7];
    const float* a_dst1 = (const float*)d_in[8];
    const float* b1     = (const float*)d_in[9];
    const float* ln_g   = (const float*)d_in[10];
    const float* ln_b   = (const float*)d_in[11];
    const float* W_ih   = (const float*)d_in[12];
    const float* W_hh   = (const float*)d_in[13];
    const float* b_ih   = (const float*)d_in[14];
    const float* b_hh   = (const float*)d_in[15];

    float* out = (float*)d_out;

    const int EB   = (EP + 255) / 256;
    const int SMB  = (Nn * 32 + 255) / 256;    // warp-per-node grid = 1250
    const int NB32 = (Nn + 31) / 32;           // 313

    k_init<<<(192 * 64 + 255) / 256, 256>>>(W_ih, W_hh);
    k_count<<<EB, 256>>>(ei);
    k_scan<<<1, 1024>>>();
    k_scatter<<<EB, 256>>>(ei);

    // All 6 timesteps' layer-0 GEMMs are independent -> one wide launch.
    k_l0_gemm_all<<<dim3(NB32, Tt), 256>>>(x, W0, a_src0, a_dst0);

    bool haveAlpha = (long long)out_size >= (long long)Nn * 64 + (long long)EP * 4;

    for (int t = 0; t < Tt; t++) {
        k_softmax_fused<<<SMB, 256>>>(t, nullptr);
        k_aggr0<<<Nn / 8, 256>>>(b0, t);
        k_l1_gemm<<<NB32, 256>>>(W1, a_src1, a_dst1);
        float* oa = (t == Tt - 1 && haveAlpha) ? (out + (size_t)Nn * 64) : nullptr;
        k_softmax_fused<<<SMB, 256>>>(Tt, oa);
        k_aggr1<<<Nn, 128>>>(b1, ln_g, ln_b, t);
    }
    // GRU: wide input-gate GEMM over all (t,n), then register-weight recurrence.
    k_gi_all<<<Nn * Tt / 32, 192>>>(b_ih);
    k_gru_all<<<Nn / 16, 192>>>(b_hh, out);

    long long tail = (long long)out_size - ((long long)Nn * 64 + (long long)EP * 4);
    if (tail >= 4LL * EP) {
        k_write_edges<<<EB, 256>>>(ei, out, 1);
    } else if (tail >= 2LL * EP) {
        k_write_edges<<<EB, 256>>>(ei, out, 0);
    }
}

// round 17
// speedup vs baseline: 1.5041x; 1.2519x over previous
#include <cuda_runtime.h>
#include <cuda_fp16.h>

// Problem constants (fixed by the dataset)
#define Nn 10000
#define Tt 6
#define Ff 64
#define Ee 160000
#define EP 170000   // Ee + Nn self loops
#define FULLMASK 0xffffffffu

// ---------------- scratch (device globals; no allocations allowed) -------------
__device__ __align__(16) __half g_xw0[Tt * Nn * 64];          // layer0 features, per t
__device__ __align__(16) float  g_h0[Tt * Nn * 64];           // layer0 out, per t
__device__ __align__(16) __half g_xw1[(size_t)Tt * Nn * 256]; // layer1 features, per t
// head-sum slices: 0..Tt-1 layer0, Tt..2Tt-1 layer1
__device__ __align__(16) float  g_ssrc[2 * Tt * Nn * 4];
__device__ __align__(16) float  g_sdst[2 * Tt * Nn * 4];
__device__ __align__(16) float  g_alpha[(size_t)Tt * EP * 4]; // per-t alpha (reused L0/L1)
__device__ __align__(16) float  g_ht[Tt * Nn * 64];
__device__ __align__(16) float  g_gi[(size_t)Tt * Nn * 192];
__device__ float g_Wt_ih[64 * 192];
__device__ float g_Wt_hh[64 * 192];
__device__ int g_deg[Nn];
__device__ int g_rowptr[Nn + 1];
__device__ int g_cursor[Nn];
__device__ int g_csr_src[EP];
__device__ int g_csr_dst[EP];
__device__ int g_csr_eid[EP];

// ---------------- inline edge dtype detect (one thread/block, shared flag) ------
__device__ __forceinline__ int block_detect64(const void* ei) {
    __shared__ int sIs64;
    if (threadIdx.x == 0) {
        const int* w = (const int*)ei;
        int zeros = 0;
#pragma unroll
        for (int i = 0; i < 16; i++)
            if (w[2 * i + 1] == 0) zeros++;
        sIs64 = (zeros > 8) ? 1 : 0;
    }
    __syncthreads();
    return sIs64;
}

__device__ __forceinline__ int edge_val(const void* ei, int idx, int is64) {
    if (is64) return (int)((const long long*)ei)[idx];
    return ((const int*)ei)[idx];
}

// ---------------- init: zero deg, transpose GRU weights -------------------------
__global__ void k_init(const float* __restrict__ W_ih, const float* __restrict__ W_hh) {
    int i = blockIdx.x * 256 + threadIdx.x;
    if (i < Nn) g_deg[i] = 0;
    if (i < 192 * 64) {
        int kk = i / 64, j = i % 64;
        g_Wt_ih[j * 192 + kk] = W_ih[i];
        g_Wt_hh[j * 192 + kk] = W_hh[i];
    }
}

// ---------------- CSR build (dst-major) -----------------------------------------
__global__ void k_count(const void* __restrict__ ei) {
    int is64 = block_detect64(ei);
    int e = blockIdx.x * 256 + threadIdx.x;
    if (e >= EP) return;
    int d = (e < Ee) ? edge_val(ei, Ee + e, is64) : (e - Ee);
    atomicAdd(&g_deg[d], 1);
}

__global__ void k_scan() {
    __shared__ int wsum[32];
    int tid = threadIdx.x;
    const int IT = 10;
    int base = tid * IT;
    int vals[IT];
    int s = 0;
#pragma unroll
    for (int i = 0; i < IT; i++) {
        int idx = base + i;
        int v = (idx < Nn) ? g_deg[idx] : 0;
        vals[i] = s;
        s += v;
    }
    int lane = tid & 31, w = tid >> 5;
    int inc = s;
    for (int o = 1; o < 32; o <<= 1) {
        int y = __shfl_up_sync(FULLMASK, inc, o);
        if (lane >= o) inc += y;
    }
    if (lane == 31) wsum[w] = inc;
    __syncthreads();
    if (w == 0) {
        int v = wsum[lane];
        for (int o = 1; o < 32; o <<= 1) {
            int y = __shfl_up_sync(FULLMASK, v, o);
            if (lane >= o) v += y;
        }
        wsum[lane] = v;
    }
    __syncthreads();
    int excl = inc - s + ((w > 0) ? wsum[w - 1] : 0);
#pragma unroll
    for (int i = 0; i < IT; i++) {
        int idx = base + i;
        if (idx < Nn) {
            g_rowptr[idx] = excl + vals[i];
            g_cursor[idx] = excl + vals[i];
        }
    }
    if (tid == 1023) g_rowptr[Nn] = wsum[31];
}

__global__ void k_scatter(const void* __restrict__ ei) {
    int is64 = block_detect64(ei);
    int e = blockIdx.x * 256 + threadIdx.x;
    if (e >= EP) return;
    int s = (e < Ee) ? edge_val(ei, e, is64) : (e - Ee);
    int d = (e < Ee) ? edge_val(ei, Ee + e, is64) : (e - Ee);
    int p = atomicAdd(&g_cursor[d], 1);
    g_csr_src[p] = s;
    g_csr_dst[p] = d;
    g_csr_eid[p] = e;
}

// ---------------- GAT layer 0 GEMM + head sums, ALL timesteps (grid.y = t) ------
__global__ void k_l0_gemm_all(const float* __restrict__ x, const float* __restrict__ W0,
                              const float* __restrict__ a_src, const float* __restrict__ a_dst) {
    __shared__ float sW[64 * 64];
    __shared__ __align__(16) float sx[32][64];
    int tid = threadIdx.x;
    int t = blockIdx.y;
    int n0 = blockIdx.x * 32;
    for (int i = tid; i < 64 * 64; i += 256) sW[i] = W0[i];
    for (int i = tid; i < 32 * 64; i += 256) {
        int r = i >> 6, c = i & 63;
        int n = n0 + r;
        sx[r][c] = (n < Nn) ? x[(size_t)n * (Tt * Ff) + t * Ff + c] : 0.f;
    }
    __syncthreads();
    int r4 = tid >> 6, c = tid & 63;
    float acc[8];
#pragma unroll
    for (int q = 0; q < 8; q++) acc[q] = 0.f;
#pragma unroll
    for (int j4 = 0; j4 < 16; j4++) {
        float w0 = sW[(4 * j4 + 0) * 64 + c];
        float w1 = sW[(4 * j4 + 1) * 64 + c];
        float w2 = sW[(4 * j4 + 2) * 64 + c];
        float w3 = sW[(4 * j4 + 3) * 64 + c];
#pragma unroll
        for (int q = 0; q < 8; q++) {
            float4 xv = *(const float4*)&sx[r4 + 4 * q][4 * j4];
            acc[q] += xv.x * w0 + xv.y * w1 + xv.z * w2 + xv.w * w3;
        }
    }
    float as = a_src[c], ad = a_dst[c];
    __half* xw0 = g_xw0 + (size_t)t * Nn * 64;
    float* ssrc = g_ssrc + (size_t)t * Nn * 4;
    float* sdst = g_sdst + (size_t)t * Nn * 4;
#pragma unroll
    for (int q = 0; q < 8; q++) {
        int row = n0 + r4 + 4 * q;
        float pr = acc[q] * as, pd = acc[q] * ad;
#pragma unroll
        for (int o = 8; o > 0; o >>= 1) {
            pr += __shfl_down_sync(FULLMASK, pr, o);
            pd += __shfl_down_sync(FULLMASK, pd, o);
        }
        if (row < Nn) {
            xw0[row * 64 + c] = __float2half(acc[q]);
            if ((c & 15) == 0) {
                ssrc[row * 4 + (c >> 4)] = pr;
                sdst[row * 4 + (c >> 4)] = pd;
            }
        }
    }
}

// ---------------- GAT layer 1 GEMM + head sums, ALL timesteps (grid.y = t) ------
__global__ void k_l1_gemm_all(const float* __restrict__ W1, const float* __restrict__ a_src,
                              const float* __restrict__ a_dst) {
    __shared__ __align__(16) float sx[32][64];
    __shared__ float rs[32][8], rd[32][8];
    int tid = threadIdx.x;  // 256
    int t = blockIdx.y;
    int n0 = blockIdx.x * 32;
    const float* h0 = g_h0 + (size_t)t * Nn * 64;
    for (int i = tid; i < 32 * 64; i += 256) {
        int r = i >> 6, c = i & 63;
        int n = n0 + r;
        sx[r][c] = (n < Nn) ? h0[n * 64 + c] : 0.f;
    }
    __syncthreads();
    float acc[32];
#pragma unroll
    for (int r = 0; r < 32; r++) acc[r] = 0.f;
#pragma unroll 4
    for (int j4 = 0; j4 < 16; j4++) {
        float w0 = W1[(4 * j4 + 0) * 256 + tid];
        float w1 = W1[(4 * j4 + 1) * 256 + tid];
        float w2 = W1[(4 * j4 + 2) * 256 + tid];
        float w3 = W1[(4 * j4 + 3) * 256 + tid];
#pragma unroll
        for (int r = 0; r < 32; r++) {
            float4 xv = *(const float4*)&sx[r][4 * j4];
            acc[r] += xv.x * w0 + xv.y * w1 + xv.z * w2 + xv.w * w3;
        }
    }
    float as = a_src[tid], ad = a_dst[tid];
    int lane = tid & 31, w8 = tid >> 5;
    __half* xw1 = g_xw1 + (size_t)t * Nn * 256;
#pragma unroll
    for (int r = 0; r < 32; r++) {
        int n = n0 + r;
        if (n < Nn) xw1[(size_t)n * 256 + tid] = __float2half(acc[r]);
        float pr = acc[r] * as, pd = acc[r] * ad;
#pragma unroll
        for (int o = 16; o > 0; o >>= 1) {
            pr += __shfl_down_sync(FULLMASK, pr, o);
            pd += __shfl_down_sync(FULLMASK, pd, o);
        }
        if (lane == 0) { rs[r][w8] = pr; rd[r][w8] = pd; }
    }
    __syncthreads();
    if (tid < 128) {
        int r = tid >> 2, h = tid & 3;
        int n = n0 + r;
        if (n < Nn) {
            size_t off = (size_t)(Tt + t) * Nn * 4;
            g_ssrc[off + n * 4 + h] = rs[r][2 * h] + rs[r][2 * h + 1];
            g_sdst[off + n * 4 + h] = rd[r][2 * h] + rd[r][2 * h + 1];
        }
    }
}

// ---------------- fused edge-logit + segment softmax, ALL t (warp/(node,t)) -----
// sliceBase: 0 for layer0, Tt for layer1. Alpha written to per-t slice.
__global__ void k_sm_all(int sliceBase, float* __restrict__ outAlpha) {
    int gw = (blockIdx.x * 256 + threadIdx.x) >> 5;
    int lane = threadIdx.x & 31;
    if (gw >= Nn * Tt) return;
    int t = gw / Nn, d = gw - t * Nn;
    const float4* ssrc4 = (const float4*)g_ssrc + (size_t)(sliceBase + t) * Nn;
    const float4* sdst4 = (const float4*)g_sdst + (size_t)(sliceBase + t) * Nn;
    float4* al4 = (float4*)g_alpha + (size_t)t * EP;
    int p0 = g_rowptr[d], p1 = g_rowptr[d + 1];
    int deg = p1 - p0;
    float4 sd = sdst4[d];
    bool wr = (outAlpha != nullptr) && (t == Tt - 1);

    if (deg <= 32) {
        int p = p0 + lane;
        bool act = lane < deg;
        int sidx = g_csr_src[act ? p : p0];
        float4 a = ssrc4[sidx];
        float l0 = a.x + sd.x; l0 = l0 > 0.f ? l0 : 0.2f * l0;
        float l1 = a.y + sd.y; l1 = l1 > 0.f ? l1 : 0.2f * l1;
        float l2 = a.z + sd.z; l2 = l2 > 0.f ? l2 : 0.2f * l2;
        float l3 = a.w + sd.w; l3 = l3 > 0.f ? l3 : 0.2f * l3;
        float m0 = act ? l0 : -1e30f, m1 = act ? l1 : -1e30f;
        float m2 = act ? l2 : -1e30f, m3 = act ? l3 : -1e30f;
#pragma unroll
        for (int o = 16; o > 0; o >>= 1) {
            m0 = fmaxf(m0, __shfl_xor_sync(FULLMASK, m0, o));
            m1 = fmaxf(m1, __shfl_xor_sync(FULLMASK, m1, o));
            m2 = fmaxf(m2, __shfl_xor_sync(FULLMASK, m2, o));
            m3 = fmaxf(m3, __shfl_xor_sync(FULLMASK, m3, o));
        }
        float e0 = act ? __expf(l0 - m0) : 0.f;
        float e1 = act ? __expf(l1 - m1) : 0.f;
        float e2 = act ? __expf(l2 - m2) : 0.f;
        float e3 = act ? __expf(l3 - m3) : 0.f;
        float s0 = e0, s1 = e1, s2 = e2, s3 = e3;
#pragma unroll
        for (int o = 16; o > 0; o >>= 1) {
            s0 += __shfl_xor_sync(FULLMASK, s0, o);
            s1 += __shfl_xor_sync(FULLMASK, s1, o);
            s2 += __shfl_xor_sync(FULLMASK, s2, o);
            s3 += __shfl_xor_sync(FULLMASK, s3, o);
        }
        if (act) {
            float4 e = make_float4(e0 / (s0 + 1e-16f), e1 / (s1 + 1e-16f),
                                   e2 / (s2 + 1e-16f), e3 / (s3 + 1e-16f));
            al4[p] = e;
            if (wr) ((float4*)outAlpha)[g_csr_eid[p]] = e;
        }
        return;
    }

    // slow path: stash logits/exp in the alpha slice itself (3 passes)
    float m0 = -1e30f, m1 = -1e30f, m2 = -1e30f, m3 = -1e30f;
    for (int p = p0 + lane; p < p1; p += 32) {
        float4 a = ssrc4[g_csr_src[p]];
        float l0 = a.x + sd.x; l0 = l0 > 0.f ? l0 : 0.2f * l0;
        float l1 = a.y + sd.y; l1 = l1 > 0.f ? l1 : 0.2f * l1;
        float l2 = a.z + sd.z; l2 = l2 > 0.f ? l2 : 0.2f * l2;
        float l3 = a.w + sd.w; l3 = l3 > 0.f ? l3 : 0.2f * l3;
        al4[p] = make_float4(l0, l1, l2, l3);
        m0 = fmaxf(m0, l0); m1 = fmaxf(m1, l1);
        m2 = fmaxf(m2, l2); m3 = fmaxf(m3, l3);
    }
#pragma unroll
    for (int o = 16; o > 0; o >>= 1) {
        m0 = fmaxf(m0, __shfl_xor_sync(FULLMASK, m0, o));
        m1 = fmaxf(m1, __shfl_xor_sync(FULLMASK, m1, o));
        m2 = fmaxf(m2, __shfl_xor_sync(FULLMASK, m2, o));
        m3 = fmaxf(m3, __shfl_xor_sync(FULLMASK, m3, o));
    }
    float s0 = 0.f, s1 = 0.f, s2 = 0.f, s3 = 0.f;
    for (int p = p0 + lane; p < p1; p += 32) {
        float4 l = al4[p];
        float e0 = __expf(l.x - m0), e1 = __expf(l.y - m1);
        float e2 = __expf(l.z - m2), e3 = __expf(l.w - m3);
        al4[p] = make_float4(e0, e1, e2, e3);
        s0 += e0; s1 += e1; s2 += e2; s3 += e3;
    }
#pragma unroll
    for (int o = 16; o > 0; o >>= 1) {
        s0 += __shfl_xor_sync(FULLMASK, s0, o);
        s1 += __shfl_xor_sync(FULLMASK, s1, o);
        s2 += __shfl_xor_sync(FULLMASK, s2, o);
        s3 += __shfl_xor_sync(FULLMASK, s3, o);
    }
    float i0 = 1.f / (s0 + 1e-16f), i1 = 1.f / (s1 + 1e-16f);
    float i2 = 1.f / (s2 + 1e-16f), i3 = 1.f / (s3 + 1e-16f);
    for (int p = p0 + lane; p < p1; p += 32) {
        float4 e = al4[p];
        e.x *= i0; e.y *= i1; e.z *= i2; e.w *= i3;
        al4[p] = e;
        if (wr) ((float4*)outAlpha)[g_csr_eid[p]] = e;
    }
}

// ---------------- layer-0 aggregation + bias + elu -> h0, ALL t -----------------
// 256 threads = 8 (node,t) tasks x 32 lanes; lane owns column pair.
__global__ void k_aggr0_all(const float* __restrict__ b0) {
    int task = blockIdx.x * 8 + (threadIdx.x >> 5);
    if (task >= Nn * Tt) return;
    int lane = threadIdx.x & 31;
    int t = task / Nn, d = task - t * Nn;
    int h = lane >> 3;
    int p0 = g_rowptr[d], p1 = g_rowptr[d + 1];
    const __half2* xw = (const __half2*)(g_xw0 + (size_t)t * Nn * 64);
    const float* alpha = g_alpha + (size_t)t * EP * 4;
    float ax = 0.f, ay = 0.f;
    int p = p0;
    for (; p + 4 <= p1; p += 4) {
        int s0 = g_csr_src[p], s1 = g_csr_src[p + 1];
        int s2 = g_csr_src[p + 2], s3 = g_csr_src[p + 3];
        float a0 = alpha[4 * p + h],       a1 = alpha[4 * (p + 1) + h];
        float a2 = alpha[4 * (p + 2) + h], a3 = alpha[4 * (p + 3) + h];
        float2 v0 = __half22float2(xw[s0 * 32 + lane]);
        float2 v1 = __half22float2(xw[s1 * 32 + lane]);
        float2 v2 = __half22float2(xw[s2 * 32 + lane]);
        float2 v3 = __half22float2(xw[s3 * 32 + lane]);
        ax += a0 * v0.x + a1 * v1.x + a2 * v2.x + a3 * v3.x;
        ay += a0 * v0.y + a1 * v1.y + a2 * v2.y + a3 * v3.y;
    }
    for (; p < p1; p++) {
        float a = alpha[4 * p + h];
        float2 v = __half22float2(xw[g_csr_src[p] * 32 + lane]);
        ax += a * v.x; ay += a * v.y;
    }
    int cc = 2 * lane;
    float v0 = ax + b0[cc];
    float v1 = ay + b0[cc + 1];
    v0 = (v0 > 0.f) ? v0 : expm1f(v0);
    v1 = (v1 > 0.f) ? v1 : expm1f(v1);
    float* h0 = g_h0 + (size_t)t * Nn * 64;
    h0[d * 64 + cc] = v0;
    h0[d * 64 + cc + 1] = v1;
}

// ---------------- layer-1 aggregation + head-mean + elu + LN -> g_ht, ALL t -----
// Block (128 threads) per (node,t); thread owns column pair; head = tid>>5.
__global__ void k_aggr1_all(const float* __restrict__ b1, const float* __restrict__ ln_g,
                            const float* __restrict__ ln_b) {
    int task = blockIdx.x;
    int t = task / Nn, d = task - t * Nn;
    int tid = threadIdx.x;  // 128
    int h = tid >> 5;
    int p0 = g_rowptr[d], p1 = g_rowptr[d + 1];
    const __half2* xw = (const __half2*)(g_xw1 + (size_t)t * Nn * 256);
    const float* alpha = g_alpha + (size_t)t * EP * 4;
    float ax = 0.f, ay = 0.f;
    int p = p0;
    for (; p + 4 <= p1; p += 4) {
        int s0 = g_csr_src[p], s1 = g_csr_src[p + 1];
        int s2 = g_csr_src[p + 2], s3 = g_csr_src[p + 3];
        float a0 = alpha[4 * p + h],       a1 = alpha[4 * (p + 1) + h];
        float a2 = alpha[4 * (p + 2) + h], a3 = alpha[4 * (p + 3) + h];
        float2 v0 = __half22float2(xw[(size_t)s0 * 128 + tid]);
        float2 v1 = __half22float2(xw[(size_t)s1 * 128 + tid]);
        float2 v2 = __half22float2(xw[(size_t)s2 * 128 + tid]);
        float2 v3 = __half22float2(xw[(size_t)s3 * 128 + tid]);
        ax += a0 * v0.x + a1 * v1.x + a2 * v2.x + a3 * v3.x;
        ay += a0 * v0.y + a1 * v1.y + a2 * v2.y + a3 * v3.y;
    }
    for (; p < p1; p++) {
        float a = alpha[4 * p + h];
        float2 v = __half22float2(xw[(size_t)g_csr_src[p] * 128 + tid]);
        ax += a * v.x; ay += a * v.y;
    }
    __shared__ float2 sh2[128];
    sh2[tid] = make_float2(ax, ay);
    __syncthreads();
    if (tid < 32) {
        float2 a0 = sh2[tid], a1 = sh2[tid + 32], a2 = sh2[tid + 64], a3 = sh2[tid + 96];
        int cc = 2 * tid;
        float v0 = (a0.x + a1.x + a2.x + a3.x) * 0.25f + b1[cc];
        float v1 = (a0.y + a1.y + a2.y + a3.y) * 0.25f + b1[cc + 1];
        v0 = (v0 > 0.f) ? v0 : expm1f(v0);
        v1 = (v1 > 0.f) ? v1 : expm1f(v1);
        float s = v0 + v1, q = v0 * v0 + v1 * v1;
#pragma unroll
        for (int o = 16; o > 0; o >>= 1) {
            s += __shfl_xor_sync(FULLMASK, s, o);
            q += __shfl_xor_sync(FULLMASK, q, o);
        }
        float mean = s * (1.f / 64.f);
        float var = q * (1.f / 64.f) - mean * mean;
        float is = rsqrtf(var + 1e-5f);
        float* ht = g_ht + (size_t)t * Nn * 64;
        ht[d * 64 + cc]     = (v0 - mean) * is * ln_g[cc]     + ln_b[cc];
        ht[d * 64 + cc + 1] = (v1 - mean) * is * ln_g[cc + 1] + ln_b[cc + 1];
    }
}

// ---------------- GRU input-gate GEMM over all (t,n) rows -----------------------
__global__ void k_gi_all(const float* __restrict__ b_ih) {
    __shared__ __align__(16) float sx[32][64];
    int tid = threadIdx.x;  // 192
    int r0 = blockIdx.x * 32;
    for (int i = tid; i < 32 * 64; i += 192) {
        int r = i >> 6, c = i & 63;
        sx[r][c] = g_ht[(size_t)(r0 + r) * 64 + c];
    }
    float w[64];
#pragma unroll
    for (int j = 0; j < 64; j++) w[j] = g_Wt_ih[j * 192 + tid];
    __syncthreads();
    float acc[32];
#pragma unroll
    for (int r = 0; r < 32; r++) acc[r] = 0.f;
#pragma unroll 8
    for (int j4 = 0; j4 < 16; j4++) {
#pragma unroll
        for (int r = 0; r < 32; r++) {
            float4 xv = *(const float4*)&sx[r][4 * j4];
            acc[r] += xv.x * w[4 * j4] + xv.y * w[4 * j4 + 1]
                    + xv.z * w[4 * j4 + 2] + xv.w * w[4 * j4 + 3];
        }
    }
    float b = b_ih[tid];
#pragma unroll
    for (int r = 0; r < 32; r++)
        g_gi[(size_t)(r0 + r) * 192 + tid] = acc[r] + b;
}

// ---------------- GRU recurrence: single kernel over all timesteps --------------
__global__ void k_gru_all(const float* __restrict__ b_hh, float* __restrict__ outp) {
    __shared__ __align__(16) float shh[16][64];
    __shared__ float gh[16][192];
    int tid = threadIdx.x;  // 192
    int n0 = blockIdx.x * 16;
    float w[64];
#pragma unroll
    for (int j = 0; j < 64; j++) w[j] = g_Wt_hh[j * 192 + tid];
    float bh = b_hh[tid];
    for (int i = tid; i < 16 * 64; i += 192) shh[i >> 6][i & 63] = 0.f;
    __syncthreads();
    for (int t = 0; t < Tt; t++) {
        float ah[16];
#pragma unroll
        for (int r = 0; r < 16; r++) ah[r] = 0.f;
#pragma unroll 8
        for (int j4 = 0; j4 < 16; j4++) {
#pragma unroll
            for (int r = 0; r < 16; r++) {
                float4 hv = *(const float4*)&shh[r][4 * j4];
                ah[r] += hv.x * w[4 * j4] + hv.y * w[4 * j4 + 1]
                       + hv.z * w[4 * j4 + 2] + hv.w * w[4 * j4 + 3];
            }
        }
#pragma unroll
        for (int r = 0; r < 16; r++) gh[r][tid] = ah[r] + bh;
        __syncthreads();
        const float* gi = g_gi + ((size_t)t * Nn + n0) * 192;
        for (int i = tid; i < 16 * 64; i += 192) {
            int r = i >> 6, kk = i & 63;
            float ir = gi[r * 192 + kk];
            float iz = gi[r * 192 + 64 + kk];
            float ig = gi[r * 192 + 128 + kk];
            float hr = gh[r][kk], hz = gh[r][64 + kk], hg = gh[r][128 + kk];
            float rr = 1.f / (1.f + __expf(-(ir + hr)));
            float zz = 1.f / (1.f + __expf(-(iz + hz)));
            float gg = tanhf(ig + rr * hg);
            float hn = (1.f - zz) * gg + zz * shh[r][kk];
            shh[r][kk] = hn;
            if (t == Tt - 1) outp[(n0 + r) * 64 + kk] = hn;
        }
        __syncthreads();
    }
}

// ---------------- output writers ------------------------------------------------
__global__ void k_write_edges(const void* __restrict__ ei, float* __restrict__ out,
                              int mode) {
    int is64 = block_detect64(ei);
    int e = blockIdx.x * 256 + threadIdx.x;
    if (e >= EP) return;
    int s = (e < Ee) ? edge_val(ei, e, is64) : (e - Ee);
    int d = (e < Ee) ? edge_val(ei, Ee + e, is64) : (e - Ee);
    size_t base = (size_t)Nn * 64 + (size_t)EP * 4;
    if (mode == 1) {
        long long* p = (long long*)(out + base);
        p[e] = (long long)s;
        p[EP + e] = (long long)d;
    } else {
        out[base + e] = (float)s;
        out[base + EP + e] = (float)d;
    }
}

// ---------------- host launch ---------------------------------------------------
extern "C" void kernel_launch(void* const* d_in, const int* in_sizes, int n_in,
                              void* d_out, int out_size) {
    const float* x      = (const float*)d_in[0];
    const void*  ei     = (const void*)d_in[1];
    const float* W0     = (const float*)d_in[2];
    const float* a_src0 = (const float*)d_in[3];
    const float* a_dst0 = (const float*)d_in[4];
    const float* b0     = (const float*)d_in[5];
    const float* W1     = (const float*)d_in[6];
    const float* a_src1 = (const float*)d_in[7];
    const float* a_dst1 = (const float*)d_in[8];
    const float* b1     = (const float*)d_in[9];
    const float* ln_g   = (const float*)d_in[10];
    const float* ln_b   = (const float*)d_in[11];
    const float* W_ih   = (const float*)d_in[12];
    const float* W_hh   = (const float*)d_in[13];
    const float* b_ih   = (const float*)d_in[14];
    const float* b_hh   = (const float*)d_in[15];

    float* out = (float*)d_out;

    const int EB    = (EP + 255) / 256;
    const int NB32  = (Nn + 31) / 32;                 // 313
    const int SMALL = (Nn * Tt * 32 + 255) / 256;     // 7500 (warp per (node,t))
    const int AGG0B = (Nn * Tt + 7) / 8;              // 7500

    k_init<<<(192 * 64 + 255) / 256, 256>>>(W_ih, W_hh);
    k_count<<<EB, 256>>>(ei);
    k_scan<<<1, 1024>>>();
    k_scatter<<<EB, 256>>>(ei);

    bool haveAlpha = (long long)out_size >= (long long)Nn * 64 + (long long)EP * 4;
    float* oa = haveAlpha ? (out + (size_t)Nn * 64) : nullptr;

    // Stage-batched pipeline: every stage covers all 6 timesteps in one launch.
    k_l0_gemm_all<<<dim3(NB32, Tt), 256>>>(x, W0, a_src0, a_dst0);
    k_sm_all<<<SMALL, 256>>>(0, nullptr);
    k_aggr0_all<<<AGG0B, 256>>>(b0);
    k_l1_gemm_all<<<dim3(NB32, Tt), 256>>>(W1, a_src1, a_dst1);
    k_sm_all<<<SMALL, 256>>>(Tt, oa);
    k_aggr1_all<<<Nn * Tt, 128>>>(b1, ln_g, ln_b);
    // GRU: wide input-gate GEMM over all (t,n), then register-weight recurrence.
    k_gi_all<<<Nn * Tt / 32, 192>>>(b_ih);
    k_gru_all<<<Nn / 16, 192>>>(b_hh, out);

    long long tail = (long long)out_size - ((long long)Nn * 64 + (long long)EP * 4);
    if (tail >= 4LL * EP) {
        k_write_edges<<<EB, 256>>>(ei, out, 1);
    } else if (tail >= 2LL * EP) {
        k_write_edges<<<EB, 256>>>(ei, out, 0);
    }
}